// round 6
// baseline (speedup 1.0000x reference)
#include <cuda_runtime.h>

#define BATCH 64
#define FEAT  784
#define DIM   1001
#define DIMSQ (DIM * DIM)        // 1002001; DIMSQ % 4 == 1, DIM % 4 == 1
#define ROWS_PER_CTA 112
#define CTAS_X 9                 // 9*112 = 1008 >= 1001

// Row-start element offset o = b*DIMSQ + i*DIM  ->  o mod 4 == (b+i) & 3.
// Aligned quads start at j == A (mod 4), A = (-(b+i)) & 3.
// 256 threads: thread t stores the quad j = A + 4t (one STG.128 per row),
// slice taken from register window w[0..7] = s[4t .. 4t+8).
// Threads 250+ write the <=5 scalar edge elements (uniform si*s[j]; zero-padded
// smem makes j >= FEAT come out 0 automatically).
__global__ void __launch_bounds__(256, 4) amp_kernel(const float* __restrict__ x,
                                                     float* __restrict__ out) {
    __shared__ float s_sm[1032];     // scaled state, zero-padded past FEAT
    __shared__ float red[8];
    __shared__ float s_inv;

    const int tid = threadIdx.x;
    const int b   = blockIdx.y;
    const float* xb = x + b * FEAT;

    // ---- norm (once per CTA; ~single wave => ~4 per SM) ----
    float p = 0.0f;
    for (int j = tid; j < FEAT; j += 256) { float v = xb[j]; p += v * v; }
    #pragma unroll
    for (int o = 16; o > 0; o >>= 1) p += __shfl_xor_sync(0xFFFFFFFFu, p, o);
    if ((tid & 31) == 0) red[tid >> 5] = p;
    __syncthreads();
    if (tid == 0) {
        float s = 0.0f;
        #pragma unroll
        for (int k = 0; k < 8; k++) s += red[k];
        s_inv = rsqrtf(s);
    }
    __syncthreads();
    const float inv = s_inv;

    for (int j = tid; j < 1032; j += 256)
        s_sm[j] = (j < FEAT) ? xb[j] * inv : 0.0f;
    __syncthreads();

    // ---- register window: s[4t .. 4t+8) ----
    float w[8];
    {
        const float4 a0 = *reinterpret_cast<const float4*>(&s_sm[4 * tid]);
        const float4 a1 = *reinterpret_cast<const float4*>(&s_sm[4 * tid + 4]);
        w[0]=a0.x; w[1]=a0.y; w[2]=a0.z; w[3]=a0.w;
        w[4]=a1.x; w[5]=a1.y; w[6]=a1.z; w[7]=a1.w;
    }

    const int i0   = blockIdx.x * ROWS_PER_CTA;
    const int iend = (i0 + ROWS_PER_CTA < DIM) ? (i0 + ROWS_PER_CTA) : DIM;

    for (int i = i0; i < iend; ++i) {
        const float si = s_sm[i];                              // broadcast LDS
        float* rowp = out + (size_t)b * DIMSQ + (size_t)i * DIM;
        const int A = (-(b + i)) & 3;

        // Per-phase constants:
        //  A=0: nq=250, edges: j=1000
        //  A=1: nq=250, edges: j=0
        //  A=2: nq=249, edges: j=0,1,998,999,1000
        //  A=3: nq=249, edges: j=0,1,2,999,1000
        switch (A) {
            case 0: {
                if (tid < 250) {
                    float4 v = make_float4(si*w[0], si*w[1], si*w[2], si*w[3]);
                    __stcs(reinterpret_cast<float4*>(rowp + 4 * tid), v);
                } else if (tid == 250) {
                    rowp[1000] = si * s_sm[1000];
                }
                break;
            }
            case 1: {
                if (tid < 250) {
                    float4 v = make_float4(si*w[1], si*w[2], si*w[3], si*w[4]);
                    __stcs(reinterpret_cast<float4*>(rowp + 1 + 4 * tid), v);
                } else if (tid == 250) {
                    rowp[0] = si * s_sm[0];
                }
                break;
            }
            case 2: {
                if (tid < 249) {
                    float4 v = make_float4(si*w[2], si*w[3], si*w[4], si*w[5]);
                    __stcs(reinterpret_cast<float4*>(rowp + 2 + 4 * tid), v);
                } else if (tid < 254) {
                    const int k = tid - 249;                   // 0..4
                    const int j = (k < 2) ? k : (996 + k);     // 0,1,998,999,1000
                    rowp[j] = si * s_sm[j];
                }
                break;
            }
            default: {
                if (tid < 249) {
                    float4 v = make_float4(si*w[3], si*w[4], si*w[5], si*w[6]);
                    __stcs(reinterpret_cast<float4*>(rowp + 3 + 4 * tid), v);
                } else if (tid < 254) {
                    const int k = tid - 249;                   // 0..4
                    const int j = (k < 3) ? k : (996 + k);     // 0,1,2,999,1000
                    rowp[j] = si * s_sm[j];
                }
                break;
            }
        }
    }
}

extern "C" void kernel_launch(void* const* d_in, const int* in_sizes, int n_in,
                              void* d_out, int out_size) {
    const float* x   = (const float*)d_in[0];
    float*       out = (float*)d_out;
    amp_kernel<<<dim3(CTAS_X, BATCH), 256>>>(x, out);
}

// round 7
// speedup vs baseline: 1.2565x; 1.2565x over previous
#include <cuda_runtime.h>

#define BATCH 64
#define FEAT  784
#define DIM   1001
#define DIMSQ (DIM * DIM)        // 1002001; DIM % 4 == 1
#define ROWS_PER_CTA 14
#define CTAS_X 72                // 72*14 = 1008 >= 1001

// Row-start element offset o = b*DIMSQ + i*DIM  ->  o mod 4 == (b + i) & 3.
// Aligned quads start at j == A (mod 4), A = (-(b+i)) & 3.
// Thread t register windows:
//   w0[0..7] = s[4t .. 4t+8)       pass-0 quad j = A + 4t      (slice w0[A..A+3])
//   w1[0..7] = s[512+4t .. +8)     pass-1 quad j = A + 512 + 4t
__global__ void __launch_bounds__(128) amp_kernel(const float* __restrict__ x,
                                                  float* __restrict__ out) {
    __shared__ float  s_sm[1032];          // scaled state, zero-padded past FEAT
    __shared__ float  red[4];
    __shared__ float  s_inv;

    const int tid = threadIdx.x;
    const int b   = blockIdx.y;
    const float* xb = x + b * FEAT;                       // 16B-aligned (784*4B)
    const float4* xb4 = reinterpret_cast<const float4*>(xb);   // 196 float4s
    float4* s_sm4 = reinterpret_cast<float4*>(s_sm);           // 258 float4s

    // ---- vectorized norm: 196 = 128 + 68 float4 loads ----
    float4 v0 = make_float4(0.f, 0.f, 0.f, 0.f);
    float4 v1 = make_float4(0.f, 0.f, 0.f, 0.f);
    v0 = xb4[tid];                                        // tid < 128 < 196: valid
    if (tid < 68) v1 = xb4[tid + 128];
    float p = v0.x * v0.x + v0.y * v0.y + v0.z * v0.z + v0.w * v0.w
            + v1.x * v1.x + v1.y * v1.y + v1.z * v1.z + v1.w * v1.w;
    #pragma unroll
    for (int o = 16; o > 0; o >>= 1) p += __shfl_xor_sync(0xFFFFFFFFu, p, o);
    if ((tid & 31) == 0) red[tid >> 5] = p;
    __syncthreads();
    if (tid == 0) s_inv = rsqrtf(red[0] + red[1] + red[2] + red[3]);
    __syncthreads();
    const float inv = s_inv;

    // ---- scaled state to smem (float4 stores) + zero pad ----
    {
        float4 sv0 = make_float4(v0.x * inv, v0.y * inv, v0.z * inv, v0.w * inv);
        s_sm4[tid] = sv0;
        if (tid < 68) {
            float4 sv1 = make_float4(v1.x * inv, v1.y * inv, v1.z * inv, v1.w * inv);
            s_sm4[tid + 128] = sv1;
        }
        if (tid >= 68 && tid < 130)                        // float4 idx 196..257
            s_sm4[tid + 128] = make_float4(0.f, 0.f, 0.f, 0.f);
    }
    __syncthreads();

    // ---- register windows ----
    float w0[8], w1[8];
    {
        const float4 a0 = *reinterpret_cast<const float4*>(&s_sm[4 * tid]);
        const float4 a1 = *reinterpret_cast<const float4*>(&s_sm[4 * tid + 4]);
        const float4 b0 = *reinterpret_cast<const float4*>(&s_sm[512 + 4 * tid]);
        const float4 b1 = *reinterpret_cast<const float4*>(&s_sm[512 + 4 * tid + 4]);
        w0[0]=a0.x; w0[1]=a0.y; w0[2]=a0.z; w0[3]=a0.w;
        w0[4]=a1.x; w0[5]=a1.y; w0[6]=a1.z; w0[7]=a1.w;
        w1[0]=b0.x; w1[1]=b0.y; w1[2]=b0.z; w1[3]=b0.w;
        w1[4]=b1.x; w1[5]=b1.y; w1[6]=b1.z; w1[7]=b1.w;
    }

    // ---- stream rows (identical to round-4 best) ----
    const int i0   = blockIdx.x * ROWS_PER_CTA;
    const int iend = (i0 + ROWS_PER_CTA < DIM) ? (i0 + ROWS_PER_CTA) : DIM;

    for (int i = i0; i < iend; ++i) {
        const float si = s_sm[i];                          // broadcast LDS (0 for i>=784)
        float* rowp    = out + (size_t)b * DIMSQ + (size_t)i * DIM;
        const int a    = (4 - ((b + i) & 3)) & 3;          // aligned-quad phase

        // head scalars j in [0, a)
        if (tid < a) rowp[tid] = si * s_sm[tid];
        // tail scalars j in [ts, 1001): all j >= 998 >= FEAT -> zero
        const int ts = 998 + ((a + 2) & 3);                // a=0:1000 1:1001 2:998 3:999
        if (tid >= 8 && tid < 8 + (DIM - ts)) rowp[ts + tid - 8] = 0.0f;

        float4 q0, q1;
        switch (a) {
            case 0: q0 = make_float4(w0[0], w0[1], w0[2], w0[3]);
                    q1 = make_float4(w1[0], w1[1], w1[2], w1[3]); break;
            case 1: q0 = make_float4(w0[1], w0[2], w0[3], w0[4]);
                    q1 = make_float4(w1[1], w1[2], w1[3], w1[4]); break;
            case 2: q0 = make_float4(w0[2], w0[3], w0[4], w0[5]);
                    q1 = make_float4(w1[2], w1[3], w1[4], w1[5]); break;
            default: q0 = make_float4(w0[3], w0[4], w0[5], w0[6]);
                     q1 = make_float4(w1[3], w1[4], w1[5], w1[6]); break;
        }
        q0.x *= si; q0.y *= si; q0.z *= si; q0.w *= si;
        q1.x *= si; q1.y *= si; q1.z *= si; q1.w *= si;

        const int j0 = a + 4 * tid;                        // <= 511, always in-row
        __stcs(reinterpret_cast<float4*>(rowp + j0), q0);
        const int j1 = j0 + 512;
        if (j1 <= DIM - 4)
            __stcs(reinterpret_cast<float4*>(rowp + j1), q1);
    }
}

extern "C" void kernel_launch(void* const* d_in, const int* in_sizes, int n_in,
                              void* d_out, int out_size) {
    const float* x   = (const float*)d_in[0];
    float*       out = (float*)d_out;
    amp_kernel<<<dim3(CTAS_X, BATCH), 128>>>(x, out);
}

// round 9
// speedup vs baseline: 1.2957x; 1.0312x over previous
#include <cuda_runtime.h>
#include <cstdint>

#define BATCH 64
#define FEAT  784
#define DIM   1001
#define DIMSQ (DIM * DIM)        // 1002001; DIM % 8 == 1, DIMSQ % 8 == 1
#define ROWS_PER_CTA 14
#define CTAS_X 72                // 72*14 = 1008 >= 1001

// 256-bit store (sm_100+): 8 x b32, requires 32B-aligned address.
#define STG256(p, a0,a1,a2,a3,a4,a5,a6,a7)                                     \
    asm volatile("st.global.v8.b32 [%0], {%1,%2,%3,%4,%5,%6,%7,%8};"           \
                 :: "l"(p),                                                    \
                    "r"(__float_as_uint(a0)), "r"(__float_as_uint(a1)),        \
                    "r"(__float_as_uint(a2)), "r"(__float_as_uint(a3)),        \
                    "r"(__float_as_uint(a4)), "r"(__float_as_uint(a5)),        \
                    "r"(__float_as_uint(a6)), "r"(__float_as_uint(a7))         \
                 : "memory")

// Row-start element offset o = b*DIMSQ + i*DIM  ->  o mod 8 == (b + i) & 7.
// 32B-aligned octets start at j == A8 (mod 8), A8 = (-(b+i)) & 7.
// Octet count NQ(A8): 125 for A8<=1, else 124 (so octets never overrun the row).
//   coverage: [A8, A8+8*NQ); head [0,A8); tail [A8+8*NQ, 1001).
// Tail always starts at j >= 994 > FEAT -> tail values are exactly 0.
__global__ void __launch_bounds__(128) amp_kernel(const float* __restrict__ x,
                                                  float* __restrict__ out) {
    __shared__ float s_sm[1032];           // scaled state, zero-padded past FEAT
    __shared__ float red[4];
    __shared__ float s_inv;

    const int tid = threadIdx.x;
    const int b   = blockIdx.y;
    const float* xb = x + b * FEAT;                            // 16B-aligned
    const float4* xb4 = reinterpret_cast<const float4*>(xb);   // 196 float4s
    float4* s_sm4 = reinterpret_cast<float4*>(s_sm);           // 258 float4s

    // ---- vectorized norm (R7-proven) ----
    float4 v0 = xb4[tid];                                      // tid < 128 < 196
    float4 v1 = make_float4(0.f, 0.f, 0.f, 0.f);
    if (tid < 68) v1 = xb4[tid + 128];
    float p = v0.x * v0.x + v0.y * v0.y + v0.z * v0.z + v0.w * v0.w
            + v1.x * v1.x + v1.y * v1.y + v1.z * v1.z + v1.w * v1.w;
    #pragma unroll
    for (int o = 16; o > 0; o >>= 1) p += __shfl_xor_sync(0xFFFFFFFFu, p, o);
    if ((tid & 31) == 0) red[tid >> 5] = p;
    __syncthreads();
    if (tid == 0) s_inv = rsqrtf(red[0] + red[1] + red[2] + red[3]);
    __syncthreads();
    const float inv = s_inv;

    {
        s_sm4[tid] = make_float4(v0.x * inv, v0.y * inv, v0.z * inv, v0.w * inv);
        if (tid < 68)
            s_sm4[tid + 128] = make_float4(v1.x * inv, v1.y * inv, v1.z * inv, v1.w * inv);
        if (tid >= 68 && tid < 130)                            // float4 idx 196..257
            s_sm4[tid + 128] = make_float4(0.f, 0.f, 0.f, 0.f);
    }
    __syncthreads();

    // ---- register window: w[0..15] = s[8t .. 8t+16) ----
    float w[16];
    #pragma unroll
    for (int q = 0; q < 4; q++) {
        const float4 a = *reinterpret_cast<const float4*>(&s_sm[8 * tid + 4 * q]);
        w[4*q+0] = a.x; w[4*q+1] = a.y; w[4*q+2] = a.z; w[4*q+3] = a.w;
    }

    const int i0   = blockIdx.x * ROWS_PER_CTA;
    const int iend = (i0 + ROWS_PER_CTA < DIM) ? (i0 + ROWS_PER_CTA) : DIM;

    for (int i = i0; i < iend; ++i) {
        const float si = s_sm[i];                              // broadcast LDS
        float* rowp    = out + (size_t)b * DIMSQ + (size_t)i * DIM;
        const int A8   = (-(b + i)) & 7;

        // head scalars j in [0, A8)
        if (tid < A8) rowp[tid] = si * s_sm[tid];

        // per-phase: NQ octets + zero tail (tail j >= 994 > FEAT)
        #define CASE(K)                                                            \
            {                                                                      \
                constexpr int NQ = ((K) <= 1) ? 125 : 124;                         \
                constexpr int TS = (K) + 8 * NQ;        /* tail start */           \
                if (tid < NQ) {                                                    \
                    float* dst = rowp + (K) + 8 * tid;  /* 32B-aligned */          \
                    STG256(dst, si*w[(K)+0], si*w[(K)+1], si*w[(K)+2],             \
                                si*w[(K)+3], si*w[(K)+4], si*w[(K)+5],             \
                                si*w[(K)+6], si*w[(K)+7]);                         \
                }                                                                  \
                if (TS < DIM && tid >= 120 && tid < 120 + (DIM - TS))              \
                    rowp[TS + (tid - 120)] = 0.0f;                                 \
            }
        switch (A8) {
            case 0: CASE(0); break;
            case 1: CASE(1); break;
            case 2: CASE(2); break;
            case 3: CASE(3); break;
            case 4: CASE(4); break;
            case 5: CASE(5); break;
            case 6: CASE(6); break;
            default: CASE(7); break;
        }
        #undef CASE
    }
}

extern "C" void kernel_launch(void* const* d_in, const int* in_sizes, int n_in,
                              void* d_out, int out_size) {
    const float* x   = (const float*)d_in[0];
    float*       out = (float*)d_out;
    amp_kernel<<<dim3(CTAS_X, BATCH), 128>>>(x, out);
}